// round 8
// baseline (speedup 1.0000x reference)
#include <cuda_runtime.h>
#include <cuda_bf16.h>

// out[b, d] = x[b, d] * clamp(diagonal[d], -0.95, 0.95)
// BATCH = 16384, LATENT_DIM = 8192, fp32. 1 GiB streamed, HBM-bound.
//
// R8: MLP=16 burst probe. TPB=128, one CTA = one full row:
//     16 front-batched LDG.128 (evict-first), clamp+scale, then 16 batched
//     STG.128 (streaming). Continues the monotone burst-length trend
//     (MLP 1/4/8 -> 6500/6718/6768 GB/s). Occ ~37% (regs ~80) — occupancy
//     proven non-binding down to 51%; this round bounds the threshold.

#define LATENT_DIM 8192
#define BATCH 16384
#define COLS4 (LATENT_DIM / 4)        // 2048 float4 per row
#define TPB 128
#define UNROLL 16                     // TPB * UNROLL == COLS4 (one row per CTA)

__global__ __launch_bounds__(TPB)
void diag_linear_kernel(const float4* __restrict__ x,
                        const float4* __restrict__ diag,
                        float4* __restrict__ out) {
    const int col = threadIdx.x;                         // 0 .. 127
    const long long off = (long long)blockIdx.x * COLS4 + col;

    // 16 independent front-batched reads: long uninterrupted read run.
    float4 v[UNROLL];
#pragma unroll
    for (int k = 0; k < UNROLL; k++)
        v[k] = __ldcs(&x[off + k * TPB]);

    // Apply clamped diagonal (32 KiB, L1/L2-hot); temp reused per k.
#pragma unroll
    for (int k = 0; k < UNROLL; k++) {
        float4 s = __ldg(&diag[col + k * TPB]);
        s.x = fminf(fmaxf(s.x, -0.95f), 0.95f);
        s.y = fminf(fmaxf(s.y, -0.95f), 0.95f);
        s.z = fminf(fmaxf(s.z, -0.95f), 0.95f);
        s.w = fminf(fmaxf(s.w, -0.95f), 0.95f);
        v[k].x *= s.x;
        v[k].y *= s.y;
        v[k].z *= s.z;
        v[k].w *= s.w;
    }

    // 16 batched streaming writes: long uninterrupted write run.
#pragma unroll
    for (int k = 0; k < UNROLL; k++)
        __stcs(&out[off + k * TPB], v[k]);
}

extern "C" void kernel_launch(void* const* d_in, const int* in_sizes, int n_in,
                              void* d_out, int out_size) {
    const float4* x    = (const float4*)d_in[0];
    const float4* diag = (const float4*)d_in[1];
    float4* out        = (float4*)d_out;

    diag_linear_kernel<<<BATCH, TPB>>>(x, diag, out);
}